// round 8
// baseline (speedup 1.0000x reference)
#include <cuda_runtime.h>

// y[i,o,n] = sum_{j=0..63} sum_k x[j,(o-1)%28, n+k-1]*W[i,j,0,k]
//                              + x[j,(o-2)%28, n+k-1]*W[i,j,1,k]
// x: (64,28,28) f32, W: (128,64,2,3) f32, y: (128,28,28) f32, zero-pad over n.
//
// SINGLE kernel, single graph node. Block: 8 ch x 4 o x 28 n, full j=64 in
// 4 phases of 16, double-buffered smem staging (LDG->regs | compute | STS | bar).
// 256 threads: warp w owns channel ib+w; lane -> (ol, ng); thread tile 1i x 4n.
// Inner math: packed fma.rn.f32x2 (validated R7). Grid (16,7)=112 blocks = 1 wave.

typedef unsigned long long u64;

static __device__ __forceinline__ u64 pk2(float a, float b) {
    u64 r; asm("mov.b64 %0, {%1, %2};" : "=l"(r) : "f"(a), "f"(b)); return r;
}
static __device__ __forceinline__ void up2(float& a, float& b, u64 v) {
    asm("mov.b64 {%0, %1}, %2;" : "=f"(a), "=f"(b) : "l"(v));
}
static __device__ __forceinline__ void fma2(u64& d, u64 a, u64 b) {
    asm("fma.rn.f32x2 %0, %1, %2, %0;" : "+l"(d) : "l"(a), "l"(b));
}
static __device__ __forceinline__ u64 lds64(unsigned sa) {
    u64 r; asm("ld.shared.b64 %0, [%1];" : "=l"(r) : "r"(sa)); return r;
}
static __device__ __forceinline__ void lds128_2x64(u64& a, u64& b, unsigned sa) {
    asm("ld.shared.v2.b64 {%0, %1}, [%2];" : "=l"(a), "=l"(b) : "r"(sa));
}

#define PJ 16   // j per phase
#define NPH 4   // phases
#define IC 8    // channels per block

__global__ __launch_bounds__(256)
void conv_full_kernel(const float* __restrict__ x,
                      const float* __restrict__ W,
                      float* __restrict__ out) {
    // x rows, padded: value for col n at slot n+1; slots 0 and 29 are zero pad.
    __shared__ __align__(16) float xs[2][PJ][6][34];
    // duplicated weight pairs: ws2[buf][jl][ch][2m..2m+1] = (w,w), m = l*3+k
    __shared__ __align__(16) float ws2[2][PJ][IC][12];

    const int tid  = threadIdx.x;
    const int warp = tid >> 5;          // 0..7 = local channel
    const int lane = tid & 31;
    const int ib = blockIdx.x * IC;     // channel base (0..120)
    const int ob = blockIdx.y * 4;      // o base (0..24)

    // ---- zero the n-pad slots (both buffers), once ----
    for (int i = tid; i < 2 * PJ * 6; i += 256) {
        int b  = i / (PJ * 6);
        int r  = i - b * (PJ * 6);
        int jl = r / 6, rl = r - jl * 6;
        xs[b][jl][rl][0]  = 0.0f;
        xs[b][jl][rl][29] = 0.0f;
    }

    // staging register buffers
    float4 xr[3];
    float  wr[3];
    int    x_jl[3], x_rl[3], x_n4[3];
    int    w_jl[3], w_il[3], w_m[3];

    // ---- LDG helper (phase p -> regs) ----
    auto stage_ldg = [&](int p) {
        #pragma unroll
        for (int q = 0; q < 3; q++) {
            int xi = tid + 256 * q;               // 0..671 (guarded)
            if (xi < 672) {
                int jl  = xi / 42;
                int rem = xi - jl * 42;
                int rl  = rem / 7;
                int n4  = rem - rl * 7;
                int row = ob - 2 + rl;
                if (row < 0) row += 28;
                x_jl[q] = jl; x_rl[q] = rl; x_n4[q] = n4;
                xr[q] = *reinterpret_cast<const float4*>(
                    x + (p * PJ + jl) * 784 + row * 28 + 4 * n4);
            }
            int wi = tid + 256 * q;               // 0..767 (exact)
            {
                int jl  = wi / 48;
                int rem = wi - jl * 48;
                int il  = rem / 6;
                int m   = rem - il * 6;
                w_jl[q] = jl; w_il[q] = il; w_m[q] = m;
                wr[q] = W[(ib + il) * 384 + (p * PJ + jl) * 6 + m];
            }
        }
    };
    // ---- STS helper (regs -> buffer b) ----
    auto stage_sts = [&](int b) {
        #pragma unroll
        for (int q = 0; q < 3; q++) {
            int xi = tid + 256 * q;
            if (xi < 672) {
                float* d = &xs[b][x_jl[q]][x_rl[q]][1 + 4 * x_n4[q]];
                d[0] = xr[q].x; d[1] = xr[q].y; d[2] = xr[q].z; d[3] = xr[q].w;
            }
            ws2[b][w_jl[q]][w_il[q]][2 * w_m[q]]     = wr[q];
            ws2[b][w_jl[q]][w_il[q]][2 * w_m[q] + 1] = wr[q];
        }
    };

    // prologue: stage phase 0 into buffer 0
    stage_ldg(0);
    stage_sts(0);
    __syncthreads();

    const int ol = lane / 7;   // 0..3 (lanes 28..31 -> 4: redundant, masked at store)
    const int ng = lane % 7;
    const int n0 = 4 * ng;

    const unsigned xs_sa = (unsigned)__cvta_generic_to_shared(&xs[0][0][0][0]);
    const unsigned ws_sa = (unsigned)__cvta_generic_to_shared(&ws2[0][0][0][0]);

    u64 acc0 = 0ULL, acc1 = 0ULL;

    for (int p = 0; p < NPH; p++) {
        const int b = p & 1;
        if (p < NPH - 1) stage_ldg(p + 1);   // LDGs in flight over the compute

        const unsigned xbase = xs_sa + (unsigned)(b * (PJ * 6 * 34)) * 4u;
        const unsigned wbase = ws_sa + (unsigned)(b * (PJ * IC * 12)) * 4u;

        #pragma unroll
        for (int jl = 0; jl < PJ; jl++) {
            const unsigned r1 = xbase + (unsigned)((jl * 6 + ol + 1) * 34 + n0) * 4u; // row o-1 (l=0)
            const unsigned r2 = xbase + (unsigned)((jl * 6 + ol) * 34 + n0) * 4u;     // row o-2 (l=1)

            u64 Q0 = lds64(r1), Q2 = lds64(r1 + 8), Q4 = lds64(r1 + 16);
            u64 R0 = lds64(r2), R2 = lds64(r2 + 8), R4 = lds64(r2 + 16);

            float q0, q1, q2, q3, q4, q5;
            up2(q0, q1, Q0); up2(q2, q3, Q2); up2(q4, q5, Q4);
            u64 Q1 = pk2(q1, q2), Q3 = pk2(q3, q4);
            float s0, s1, s2, s3, s4, s5;
            up2(s0, s1, R0); up2(s2, s3, R2); up2(s4, s5, R4);
            u64 R1 = pk2(s1, s2), R3 = pk2(s3, s4);

            const unsigned wsa = wbase + (unsigned)((jl * IC + warp) * 12) * 4u;
            u64 w01, w23, w45, w67, w89, wAB;
            lds128_2x64(w01, w23, wsa);        // l0k0, l0k1
            lds128_2x64(w45, w67, wsa + 16);   // l0k2, l1k0
            lds128_2x64(w89, wAB, wsa + 32);   // l1k1, l1k2

            // acc0: output cols (n0, n0+1)
            fma2(acc0, Q0, w01);
            fma2(acc0, Q1, w23);
            fma2(acc0, Q2, w45);
            fma2(acc0, R0, w67);
            fma2(acc0, R1, w89);
            fma2(acc0, R2, wAB);
            // acc1: output cols (n0+2, n0+3)
            fma2(acc1, Q2, w01);
            fma2(acc1, Q3, w23);
            fma2(acc1, Q4, w45);
            fma2(acc1, R2, w67);
            fma2(acc1, R3, w89);
            fma2(acc1, R4, wAB);
        }

        if (p < NPH - 1) {
            stage_sts((p + 1) & 1);
            __syncthreads();
        }
    }

    if (lane < 28) {
        const int o = ob + ol;
        float4 v;
        up2(v.x, v.y, acc0);
        up2(v.z, v.w, acc1);
        *reinterpret_cast<float4*>(out + (ib + warp) * 784 + o * 28 + n0) = v;
    }
}

extern "C" void kernel_launch(void* const* d_in, const int* in_sizes, int n_in,
                              void* d_out, int out_size) {
    const float* x = (const float*)d_in[0];  // (1,64,28,28)  = 50176 f32
    const float* W = (const float*)d_in[1];  // (128,64,2,3) = 147456 f32
    float* out = (float*)d_out;              // (1,128,28,28) = 100352 f32

    dim3 grid(16, 7);   // (i-groups of 8, o-groups of 4) = 112 blocks, 1 wave
    conv_full_kernel<<<grid, 256>>>(x, W, out);
}

// round 9
// speedup vs baseline: 1.3821x; 1.3821x over previous
#include <cuda_runtime.h>

// y[i,o,n] = sum_{j,k} x[j,(o-1)%28,n+k-1]*W[i,j,0,k] + x[j,(o-2)%28,n+k-1]*W[i,j,1,k]
// x:(64,28,28) f32, W:(128,64,2,3) f32, y:(128,28,28) f32, zero-pad over n.
//
// ONE kernel. Block = 4 ch x 2 o-rows x 28 n; 8 warps, warp w owns j in [8w,8w+8)
// (no cross-warp LDS redundancy). Partials reduced in-block through smem.
// Grid (32,14) = 448 blocks x 256 thr, 38.4KB smem, <=64 regs -> 4 blocks/SM,
// all blocks resident in one wave (~24 warps/SM). Math: packed fma.rn.f32x2.

typedef unsigned long long u64;

static __device__ __forceinline__ u64 pk2(float a, float b) {
    u64 r; asm("mov.b64 %0, {%1, %2};" : "=l"(r) : "f"(a), "f"(b)); return r;
}
static __device__ __forceinline__ void up2(float& a, float& b, u64 v) {
    asm("mov.b64 {%0, %1}, %2;" : "=f"(a), "=f"(b) : "l"(v));
}
static __device__ __forceinline__ void fma2(u64& d, u64 a, u64 b) {
    asm("fma.rn.f32x2 %0, %1, %2, %0;" : "+l"(d) : "l"(a), "l"(b));
}
static __device__ __forceinline__ u64 lds64(unsigned sa) {
    u64 r; asm("ld.shared.b64 %0, [%1];" : "=l"(r) : "r"(sa)); return r;
}
static __device__ __forceinline__ void lds128_2x64(u64& a, u64& b, unsigned sa) {
    asm("ld.shared.v2.b64 {%0, %1}, [%2];" : "=l"(a), "=l"(b) : "r"(sa));
}

#define NJW 8   // j per warp
#define NW  8   // warps per block
#define ICB 4   // channels per block
// block output tile: ICB x 2 o-rows x 28 n = 224 floats

__global__ __launch_bounds__(256, 4)
void conv_one_kernel(const float* __restrict__ x,
                     const float* __restrict__ W,
                     float* __restrict__ out) {
    // x: 3 rows per j (global rows ob-2, ob-1, ob), padded: col n -> slot n+1,
    // slots 0 and 29..33 zeroed. Row stride 34 de-phases banks.
    __shared__ __align__(16) float xs[64][3][34];     // 26112 B
    // duplicated weight pairs ws2[j][c][2m..2m+1] = (w,w), m = l*3+k
    __shared__ __align__(16) float ws2[64][ICB][12];  // 12288 B
    float* pred = &xs[0][0][0];  // reused after mainloop: [NW][224]

    const int tid = threadIdx.x;
    const int ib = blockIdx.x * ICB;   // 0..124
    const int ob = blockIdx.y * 2;     // 0..26

    // zero pad slots (0 and 29..33) per (j,row)
    for (int i = tid; i < 64 * 3; i += 256) {
        int j = i / 3, rl = i - j * 3;
        float* r = &xs[j][rl][0];
        r[0] = 0.f; r[29] = 0.f; r[30] = 0.f; r[31] = 0.f; r[32] = 0.f; r[33] = 0.f;
    }
    // stage x: 64 j x 3 rows x 7 float4 = 1344 float4 loads
    #pragma unroll
    for (int q = 0; q < 6; q++) {
        int idx4 = tid + 256 * q;
        if (idx4 < 1344) {
            int j   = idx4 / 21;
            int rem = idx4 - j * 21;
            int rl  = rem / 7;
            int n4  = rem - rl * 7;
            int row = ob - 2 + rl;
            if (row < 0) row += 28;
            float4 v = *reinterpret_cast<const float4*>(x + j * 784 + row * 28 + 4 * n4);
            float* d = &xs[j][rl][1 + 4 * n4];
            d[0] = v.x; d[1] = v.y; d[2] = v.z; d[3] = v.w;
        }
    }
    // stage weights: 4c x 64j x 6m = 1536 = 6*256 exactly
    #pragma unroll
    for (int q = 0; q < 6; q++) {
        int idx = tid + 256 * q;
        int c   = idx / 384;
        int rem = idx - c * 384;
        int j   = rem / 6;
        int m   = rem - j * 6;
        float w = W[(ib + c) * 384 + j * 6 + m];
        ws2[j][c][2 * m]     = w;
        ws2[j][c][2 * m + 1] = w;
    }
    __syncthreads();

    const int warp = tid >> 5;
    const int lane = tid & 31;
    const int ol = lane & 1;       // o-row within block
    const int ng = lane >> 1;      // 0..15; ng>=14 redundant (masked at store)
    const int n0 = 2 * ng;         // first output col of this thread's pair

    const unsigned xs_sa = (unsigned)__cvta_generic_to_shared(&xs[0][0][0]);
    const unsigned ws_sa = (unsigned)__cvta_generic_to_shared(&ws2[0][0][0]);

    u64 acc[ICB];
    #pragma unroll
    for (int c = 0; c < ICB; c++) acc[c] = 0ULL;

    const int j0 = warp * NJW;
    #pragma unroll
    for (int t = 0; t < NJW; t++) {
        const int j = j0 + t;
        // out row o = ob+ol: row (o-1) -> rl = ol+1 (l=0 weights); row (o-2) -> rl = ol (l=1)
        const unsigned r1 = xs_sa + (unsigned)(((j * 3 + ol + 1) * 34 + n0) * 4);
        const unsigned r2 = xs_sa + (unsigned)(((j * 3 + ol) * 34 + n0) * 4);

        u64 A0 = lds64(r1), A2 = lds64(r1 + 8);   // slots (n0,n0+1), (n0+2,n0+3)
        u64 B0 = lds64(r2), B2 = lds64(r2 + 8);
        float a0, a1, a2, a3, b0, b1, b2, b3;
        up2(a0, a1, A0); up2(a2, a3, A2);
        up2(b0, b1, B0); up2(b2, b3, B2);
        u64 A1 = pk2(a1, a2), B1 = pk2(b1, b2);   // slots (n0+1, n0+2)

        #pragma unroll
        for (int c = 0; c < ICB; c++) {
            const unsigned wsa = ws_sa + (unsigned)(((j * ICB + c) * 12) * 4);
            u64 w0, w1, w2, w3, w4, w5;            // warp-uniform -> broadcast LDS
            lds128_2x64(w0, w1, wsa);              // l0k0, l0k1
            lds128_2x64(w2, w3, wsa + 16);         // l0k2, l1k0
            lds128_2x64(w4, w5, wsa + 32);         // l1k1, l1k2
            // k-tap pair for k over out cols (n0,n0+1): slots (n0+k, n0+k+1)
            fma2(acc[c], A0, w0);
            fma2(acc[c], A1, w1);
            fma2(acc[c], A2, w2);
            fma2(acc[c], B0, w3);
            fma2(acc[c], B1, w4);
            fma2(acc[c], B2, w5);
        }
    }

    __syncthreads();   // all xs reads complete; safe to overwrite with partials

    if (ng < 14) {
        #pragma unroll
        for (int c = 0; c < ICB; c++) {
            float lo, hi; up2(lo, hi, acc[c]);
            float2 v = make_float2(lo, hi);
            *reinterpret_cast<float2*>(&pred[warp * 224 + (c * 2 + ol) * 28 + n0]) = v;
        }
    }
    __syncthreads();

    if (tid < 224) {
        float s = 0.f;
        #pragma unroll
        for (int w = 0; w < NW; w++) s += pred[w * 224 + tid];  // stride 224%32==0: conflict-free
        int c   = tid / 56;
        int rem = tid - c * 56;
        int o2  = rem / 28;
        int n   = rem - o2 * 28;
        out[(ib + c) * 784 + (ob + o2) * 28 + n] = s;
    }
}

extern "C" void kernel_launch(void* const* d_in, const int* in_sizes, int n_in,
                              void* d_out, int out_size) {
    const float* x = (const float*)d_in[0];  // (1,64,28,28)  = 50176 f32
    const float* W = (const float*)d_in[1];  // (128,64,2,3) = 147456 f32
    float* out = (float*)d_out;              // (1,128,28,28) = 100352 f32

    dim3 grid(32, 14);  // (i-groups of 4, o-groups of 2) = 448 blocks, one wave
    conv_one_kernel<<<grid, 256>>>(x, W, out);
}